// round 8
// baseline (speedup 1.0000x reference)
#include <cuda_runtime.h>
#include <cstdint>

#define BATCH   8
#define CIN     256
#define HWPX    4096
#define WIDTH   64
#define CR      64
#define GROUPS  32
#define GCH     8

// intermediate y = relu6(bn(conv1(x)))  : [B][64][4096] = 8.4 MB (L2-resident)
__device__ __align__(16) float g_y[(size_t)BATCH * CR * HWPX];

typedef unsigned long long u64;

// ---------------- packed f32x2 helpers ----------------
__device__ __forceinline__ u64 ffma2(u64 a, u64 b, u64 c) {
    u64 d;
    asm("fma.rn.f32x2 %0, %1, %2, %3;" : "=l"(d) : "l"(a), "l"(b), "l"(c));
    return d;
}
__device__ __forceinline__ u64 pack2(float lo, float hi) {
    u64 d;
    asm("mov.b64 %0, {%1, %2};" : "=l"(d) : "f"(lo), "f"(hi));
    return d;
}
__device__ __forceinline__ float2 unpack2(u64 v) {
    float2 r;
    asm("mov.b64 {%0, %1}, %2;" : "=f"(r.x), "=f"(r.y) : "l"(v));
    return r;
}

// ---------------------------------------------------------------------------
// K1: conv1 (256->64) + BN + ReLU6 -> g_y   (unchanged from round 7)
// grid (32 px-tiles of 128, 8 batch) = 256 CTAs, 256 threads, 2 CTAs/SM
// ---------------------------------------------------------------------------
__global__ void __launch_bounds__(256, 2)
k1_conv1(const float* __restrict__ x,
         const float* __restrict__ w1, const float* __restrict__ b1,
         const float* __restrict__ gma, const float* __restrict__ bta,
         const float* __restrict__ mu,  const float* __restrict__ var)
{
    extern __shared__ float w1t[];                                     // [256][64]
    const ulonglong2* w1tv = reinterpret_cast<const ulonglong2*>(w1t); // [256][16]

    const int tid  = threadIdx.x;
    const int lane = tid & 31;         // px quad (32 quads = 128 px)
    const int cg   = tid >> 5;         // co group: 8 co
    const int b    = blockIdx.y;
    const int px0  = blockIdx.x * 128;

    #pragma unroll 8
    for (int k = 0; k < 64; ++k) {
        int i  = tid + k * 256;
        int co = i & 63, ci = i >> 6;
        w1t[ci * 64 + co] = w1[co * 256 + ci];
    }
    __syncthreads();

    u64 acc[4][4];
    #pragma unroll
    for (int k = 0; k < 4; ++k)
        #pragma unroll
        for (int j = 0; j < 4; ++j) acc[k][j] = 0ull;

    const float4* x4 = reinterpret_cast<const float4*>(x + (size_t)b * CIN * HWPX + px0) + lane;

    float4 xv = x4[0];
    #pragma unroll 4
    for (int ci = 0; ci < 256; ++ci) {
        float4 xn = (ci < 255) ? x4[(ci + 1) * (HWPX / 4)] : xv;
        ulonglong2 wv0 = w1tv[ci * 16 + cg * 2];
        ulonglong2 wv1 = w1tv[ci * 16 + cg * 2 + 1];
        u64 xx0 = pack2(xv.x, xv.x);
        u64 xx1 = pack2(xv.y, xv.y);
        u64 xx2 = pack2(xv.z, xv.z);
        u64 xx3 = pack2(xv.w, xv.w);
        acc[0][0] = ffma2(wv0.x, xx0, acc[0][0]);
        acc[0][1] = ffma2(wv0.x, xx1, acc[0][1]);
        acc[0][2] = ffma2(wv0.x, xx2, acc[0][2]);
        acc[0][3] = ffma2(wv0.x, xx3, acc[0][3]);
        acc[1][0] = ffma2(wv0.y, xx0, acc[1][0]);
        acc[1][1] = ffma2(wv0.y, xx1, acc[1][1]);
        acc[1][2] = ffma2(wv0.y, xx2, acc[1][2]);
        acc[1][3] = ffma2(wv0.y, xx3, acc[1][3]);
        acc[2][0] = ffma2(wv1.x, xx0, acc[2][0]);
        acc[2][1] = ffma2(wv1.x, xx1, acc[2][1]);
        acc[2][2] = ffma2(wv1.x, xx2, acc[2][2]);
        acc[2][3] = ffma2(wv1.x, xx3, acc[2][3]);
        acc[3][0] = ffma2(wv1.y, xx0, acc[3][0]);
        acc[3][1] = ffma2(wv1.y, xx1, acc[3][1]);
        acc[3][2] = ffma2(wv1.y, xx2, acc[3][2]);
        acc[3][3] = ffma2(wv1.y, xx3, acc[3][3]);
        xv = xn;
    }

    float4* y4 = reinterpret_cast<float4*>(g_y + (size_t)b * CR * HWPX + px0) + lane;
    #pragma unroll
    for (int k = 0; k < 4; ++k) {
        int co0 = cg * 8 + 2 * k, co1 = co0 + 1;
        float s0  = __ldg(&gma[co0]) * rsqrtf(__ldg(&var[co0]) + 1e-5f);
        float bb0 = fmaf(__ldg(&b1[co0]), s0, __ldg(&bta[co0]) - __ldg(&mu[co0]) * s0);
        float s1  = __ldg(&gma[co1]) * rsqrtf(__ldg(&var[co1]) + 1e-5f);
        float bb1 = fmaf(__ldg(&b1[co1]), s1, __ldg(&bta[co1]) - __ldg(&mu[co1]) * s1);
        float4 r0, r1;
        float* r0f = reinterpret_cast<float*>(&r0);
        float* r1f = reinterpret_cast<float*>(&r1);
        #pragma unroll
        for (int j = 0; j < 4; ++j) {
            float2 f = unpack2(acc[k][j]);
            r0f[j] = fminf(fmaxf(fmaf(f.x, s0, bb0), 0.f), 6.f);
            r1f[j] = fminf(fmaxf(fmaf(f.y, s1, bb1), 0.f), 6.f);
        }
        y4[(size_t)co0 * (HWPX / 4)] = r0;
        y4[(size_t)co1 * (HWPX / 4)] = r1;
    }
}

// ---------------------------------------------------------------------------
// K2: fused conv2 + involution, single pass, 4 px per thread.
// grid (4 h-tiles of 16 rows, 32 groups, 8 batch) = 1024 CTAs, 256 th, 1 CTA/SM
// Thread owns 4 consecutive px (W=4*c4): ka[4px][5 rows][3 tap-pairs] = 60 u64.
// smem: xh [8ch][20r][72c] = 46080B | w2p [64cr][32f] = 8192B
// Per cr: 1 LDG.128 (y, lookahead-1) + 8 broadcast LDS.128 (w2) + 60 FFMA2
//   -> w2 LDS per-pixel cost halved vs round 7.
// ---------------------------------------------------------------------------
__global__ void __launch_bounds__(256, 1)
k2_fused(const float* __restrict__ x,
         const float* __restrict__ w2, const float* __restrict__ b2,
         float* __restrict__ out)
{
    extern __shared__ char smraw[];
    float* xh  = reinterpret_cast<float*>(smraw);                 // 46080 B
    float* w2p = reinterpret_cast<float*>(smraw + 46080);         // 8192 B

    const int tid = threadIdx.x;
    const int b   = blockIdx.z;
    const int g   = blockIdx.y;
    const int h0  = blockIdx.x * 16;
    const int px0 = h0 * WIDTH;
    const int rr  = tid >> 4;        // tile row 0..15
    const int W   = (tid & 15) * 4;  // first column of the 4-px strip

    // ---- stage x halo: 8 ch x 20 rows x 68 cols, pitch 72 ----
    const float* xb = x + ((size_t)b * CIN + g * GCH) * HWPX;
    for (int i = tid; i < 8 * 20 * 68; i += 256) {
        int c   = i / 1360;
        int rem = i - c * 1360;
        int r2  = rem / 68;
        int cc  = rem - r2 * 68;
        int hy = h0 - 2 + r2, wx = cc - 2;
        float v = 0.f;
        if ((unsigned)hy < 64u && (unsigned)wx < 64u)
            v = xb[c * HWPX + hy * WIDTH + wx];
        xh[c * 1440 + r2 * 72 + cc] = v;
    }
    // ---- stage w2p[cr][ti*6+j] = w2[(g*25+5ti+j)*64+cr], j=5 & tail = 0 ----
    for (int i = tid; i < 64 * 32; i += 256) {
        int cr  = i >> 5;
        int rem = i & 31;
        int ti  = rem / 6;
        int j   = rem - ti * 6;
        float v = (ti < 5 && j < 5) ? w2[(size_t)(g * 25 + ti * 5 + j) * 64 + cr] : 0.f;
        w2p[cr * 32 + rem] = v;
    }
    __syncthreads();

    // ---- ka[px][row][pairslot], seeded with conv2 bias ----
    u64 ka[4][5][3];
    #pragma unroll
    for (int ti = 0; ti < 5; ++ti) {
        float t0 = __ldg(b2 + g * 25 + ti * 5 + 0);
        float t1 = __ldg(b2 + g * 25 + ti * 5 + 1);
        float t2 = __ldg(b2 + g * 25 + ti * 5 + 2);
        float t3 = __ldg(b2 + g * 25 + ti * 5 + 3);
        float t4 = __ldg(b2 + g * 25 + ti * 5 + 4);
        u64 s0 = pack2(t0, t1), s1 = pack2(t2, t3), s2 = pack2(t4, 0.f);
        #pragma unroll
        for (int p = 0; p < 4; ++p) {
            ka[p][ti][0] = s0; ka[p][ti][1] = s1; ka[p][ti][2] = s2;
        }
    }

    // ---- conv2: single pass over 64 reduced channels ----
    const float4* yp = reinterpret_cast<const float4*>(g_y + (size_t)b * CR * HWPX + px0) + tid;

    float4 yv = yp[0];
    #pragma unroll 4
    for (int cr = 0; cr < 64; ++cr) {
        float4 yn = (cr < 63) ? yp[(cr + 1) * (HWPX / 4)] : yv;
        u64 yA = pack2(yv.x, yv.x);
        u64 yB = pack2(yv.y, yv.y);
        u64 yC = pack2(yv.z, yv.z);
        u64 yD = pack2(yv.w, yv.w);

        const ulonglong2* wr = reinterpret_cast<const ulonglong2*>(w2p + cr * 32);
        ulonglong2 wv[8];
        #pragma unroll
        for (int m = 0; m < 8; ++m) wv[m] = wr[m];

        #pragma unroll
        for (int ti = 0; ti < 5; ++ti) {
            #pragma unroll
            for (int k = 0; k < 3; ++k) {
                int m = ti * 3 + k;                               // u64 index 0..14
                u64 w = (m & 1) ? wv[m >> 1].y : wv[m >> 1].x;    // {w2[2m], w2[2m+1]}
                ka[0][ti][k] = ffma2(w, yA, ka[0][ti][k]);
                ka[1][ti][k] = ffma2(w, yB, ka[1][ti][k]);
                ka[2][ti][k] = ffma2(w, yC, ka[2][ti][k]);
                ka[3][ti][k] = ffma2(w, yD, ka[3][ti][k]);
            }
        }
        yv = yn;
    }

    // ---- involution + store ----
    float* ob = out + ((size_t)b * CIN + g * GCH) * HWPX + px0 + rr * WIDTH + W;
    #pragma unroll
    for (int c = 0; c < 8; ++c) {
        u64 o0 = 0ull, o1 = 0ull, o2 = 0ull, o3 = 0ull;
        #pragma unroll
        for (int ti = 0; ti < 5; ++ti) {
            const float4* xr =
                reinterpret_cast<const float4*>(xh + c * 1440 + (rr + ti) * 72 + W);
            float4 g0 = xr[0], g1 = xr[1];   // window f0..f7
            u64 p01 = pack2(g0.x, g0.y);
            u64 p23 = pack2(g0.z, g0.w);
            u64 p4x = pack2(g1.x, g1.x);
            u64 p12 = pack2(g0.y, g0.z);
            u64 p34 = pack2(g0.w, g1.x);
            u64 p5x = pack2(g1.y, g1.y);
            u64 p45 = pack2(g1.x, g1.y);
            u64 p6x = pack2(g1.z, g1.z);
            u64 p56 = pack2(g1.y, g1.z);
            u64 p7x = pack2(g1.w, g1.w);
            o0 = ffma2(ka[0][ti][0], p01, o0);
            o0 = ffma2(ka[0][ti][1], p23, o0);
            o0 = ffma2(ka[0][ti][2], p4x, o0);
            o1 = ffma2(ka[1][ti][0], p12, o1);
            o1 = ffma2(ka[1][ti][1], p34, o1);
            o1 = ffma2(ka[1][ti][2], p5x, o1);
            o2 = ffma2(ka[2][ti][0], p23, o2);
            o2 = ffma2(ka[2][ti][1], p45, o2);
            o2 = ffma2(ka[2][ti][2], p6x, o2);
            o3 = ffma2(ka[3][ti][0], p34, o3);
            o3 = ffma2(ka[3][ti][1], p56, o3);
            o3 = ffma2(ka[3][ti][2], p7x, o3);
        }
        float2 f0 = unpack2(o0), f1 = unpack2(o1), f2 = unpack2(o2), f3 = unpack2(o3);
        float4 rv;
        rv.x = f0.x + f0.y;
        rv.y = f1.x + f1.y;
        rv.z = f2.x + f2.y;
        rv.w = f3.x + f3.y;
        *reinterpret_cast<float4*>(ob + (size_t)c * HWPX) = rv;
    }
}

// ---------------------------------------------------------------------------
extern "C" void kernel_launch(void* const* d_in, const int* in_sizes, int n_in,
                              void* d_out, int out_size)
{
    const float* x   = (const float*)d_in[0];
    const float* w1  = (const float*)d_in[1];
    const float* b1  = (const float*)d_in[2];
    const float* gma = (const float*)d_in[3];
    const float* bta = (const float*)d_in[4];
    const float* mu  = (const float*)d_in[5];
    const float* var = (const float*)d_in[6];
    const float* w2  = (const float*)d_in[7];
    const float* b2  = (const float*)d_in[8];
    float* out = (float*)d_out;

    const int SMEM1 = 65536;           // w1t
    const int SMEM2 = 46080 + 8192;    // 54272 B
    cudaFuncSetAttribute(k1_conv1, cudaFuncAttributeMaxDynamicSharedMemorySize, SMEM1);
    cudaFuncSetAttribute(k2_fused, cudaFuncAttributeMaxDynamicSharedMemorySize, SMEM2);

    k1_conv1<<<dim3(32, 8), 256, SMEM1>>>(x, w1, b1, gma, bta, mu, var);
    k2_fused<<<dim3(4, 32, 8), 256, SMEM2>>>(x, w2, b2, out);
}